// round 1
// baseline (speedup 1.0000x reference)
#include <cuda_runtime.h>
#include <cuda_bf16.h>
#include <math.h>

// Problem constants
#define B_  2
#define N_  2048
#define D_  1024
#define H_  16
#define DP_ 64
#define EQ_ (3 * H_ * DP_)   // 3072
#define M_ROWS (B_ * N_)     // 4096

// Scratch (no cudaMalloc allowed)
__device__ float g_qkv[(size_t)M_ROWS * EQ_];    // 48 MB
__device__ float g_attn[(size_t)M_ROWS * D_];    // 16 MB

// ---------------------------------------------------------------------------
// Tiled SGEMM with bias: C[M,N] = A[M,K] @ B[K,N] + bias[N]
// BM=BN=128, BK=16, 256 threads, 8x8 per-thread tile
// ---------------------------------------------------------------------------
#define BM 128
#define BN 128
#define BK 16
#define TM 8
#define TN 8

__global__ __launch_bounds__(256) void sgemm_bias_kernel(
    const float* __restrict__ A, const float* __restrict__ Bm,
    const float* __restrict__ bias, float* __restrict__ C,
    int M, int N, int K)
{
    __shared__ float As[BK][BM];
    __shared__ float Bs[BK][BN];

    const int tid = threadIdx.x;
    const int block_row = blockIdx.y * BM;
    const int block_col = blockIdx.x * BN;

    const int tx = tid % (BN / TN);   // 0..15
    const int ty = tid / (BN / TN);   // 0..15

    // A-load mapping: 128 rows x 4 float4 per row = 512 float4; 2 per thread
    const int aRow  = tid >> 2;       // 0..63
    const int aCol4 = tid & 3;        // 0..3
    // B-load mapping: 16 rows x 32 float4 per row = 512 float4; 2 per thread
    const int bRow  = tid >> 5;       // 0..7
    const int bCol4 = tid & 31;       // 0..31

    float acc[TM][TN];
#pragma unroll
    for (int i = 0; i < TM; i++)
#pragma unroll
        for (int j = 0; j < TN; j++) acc[i][j] = 0.f;

    for (int k0 = 0; k0 < K; k0 += BK) {
#pragma unroll
        for (int p = 0; p < 2; p++) {
            int r = aRow + p * 64;
            float4 v = *(const float4*)&A[(size_t)(block_row + r) * K + k0 + aCol4 * 4];
            As[aCol4 * 4 + 0][r] = v.x;
            As[aCol4 * 4 + 1][r] = v.y;
            As[aCol4 * 4 + 2][r] = v.z;
            As[aCol4 * 4 + 3][r] = v.w;
        }
#pragma unroll
        for (int p = 0; p < 2; p++) {
            int r = bRow + p * 8;
            *(float4*)&Bs[r][bCol4 * 4] =
                *(const float4*)&Bm[(size_t)(k0 + r) * N + block_col + bCol4 * 4];
        }
        __syncthreads();

#pragma unroll
        for (int kk = 0; kk < BK; kk++) {
            float ra[TM], rb[TN];
#pragma unroll
            for (int i = 0; i < TM; i++) ra[i] = As[kk][ty * TM + i];
#pragma unroll
            for (int j = 0; j < TN; j++) rb[j] = Bs[kk][tx * TN + j];
#pragma unroll
            for (int i = 0; i < TM; i++)
#pragma unroll
                for (int j = 0; j < TN; j++)
                    acc[i][j] += ra[i] * rb[j];
        }
        __syncthreads();
    }

#pragma unroll
    for (int i = 0; i < TM; i++) {
        int row = block_row + ty * TM + i;
#pragma unroll
        for (int j = 0; j < TN; j += 4) {
            int col = block_col + tx * TN + j;
            float4 v;
            v.x = acc[i][j + 0] + bias[col + 0];
            v.y = acc[i][j + 1] + bias[col + 1];
            v.z = acc[i][j + 2] + bias[col + 2];
            v.w = acc[i][j + 3] + bias[col + 3];
            *(float4*)&C[(size_t)row * N + col] = v;
        }
    }
}

// ---------------------------------------------------------------------------
// Flash-attention: one CTA per (b, h, 64-query tile). 256 threads.
// qkv layout: [B*N, 3072] where col = h*192 + (q:0-63 | k:64-127 | v:128-191)
// out layout: [B*N, 1024] where col = h*64 + d
// ---------------------------------------------------------------------------
#define TLD 68   // padded row stride (floats) for 64-wide tiles

__global__ __launch_bounds__(256) void attn_kernel(
    const float* __restrict__ qkv, float* __restrict__ out)
{
    extern __shared__ float sm[];
    float* Qs  = sm;                  // 64 * 68
    float* Ks  = Qs + 64 * TLD;
    float* Vs  = Ks + 64 * TLD;
    float* Ss  = Vs + 64 * TLD;
    float* m_s = Ss + 64 * TLD;       // 64
    float* l_s = m_s + 64;            // 64
    float* f_s = l_s + 64;            // 64

    const int tid = threadIdx.x;
    const int qt = blockIdx.x;        // query tile (0..31)
    const int h  = blockIdx.y;        // head
    const int b  = blockIdx.z;        // batch

    const int tx = tid & 15;          // 0..15
    const int ty = tid >> 4;          // 0..15
    const int srow = ty * 4;
    const int scol = tx * 4;

    const int q0 = qt * 64;
    const int hq = h * 192;

    // Load Q tile (scaled by 1/sqrt(DP) = 0.125)
#pragma unroll
    for (int p = 0; p < 4; p++) {
        int idx = tid + p * 256;         // 0..1023
        int r = idx >> 4;
        int c = (idx & 15) * 4;
        float4 v = *(const float4*)&qkv[(size_t)(b * N_ + q0 + r) * EQ_ + hq + c];
        v.x *= 0.125f; v.y *= 0.125f; v.z *= 0.125f; v.w *= 0.125f;
        *(float4*)&Qs[r * TLD + c] = v;
    }
    if (tid < 64) { m_s[tid] = -3.0e38f; l_s[tid] = 0.f; }

    float acc[4][4];
#pragma unroll
    for (int i = 0; i < 4; i++)
#pragma unroll
        for (int j = 0; j < 4; j++) acc[i][j] = 0.f;

    for (int kt = 0; kt < N_ / 64; kt++) {
        __syncthreads();   // protect Ks/Vs/Ss reuse (and Qs/m/l init on iter 0)
        const int k0 = kt * 64;
#pragma unroll
        for (int p = 0; p < 4; p++) {
            int idx = tid + p * 256;
            int r = idx >> 4;
            int c = (idx & 15) * 4;
            size_t g = (size_t)(b * N_ + k0 + r) * EQ_ + hq;
            *(float4*)&Ks[r * TLD + c] = *(const float4*)&qkv[g + 64 + c];
            *(float4*)&Vs[r * TLD + c] = *(const float4*)&qkv[g + 128 + c];
        }
        __syncthreads();

        // S = Q @ K^T  (4x4 per thread)
        float s[4][4];
#pragma unroll
        for (int i = 0; i < 4; i++)
#pragma unroll
            for (int j = 0; j < 4; j++) s[i][j] = 0.f;

        for (int d = 0; d < 64; d += 4) {
            float4 qa[4], kb[4];
#pragma unroll
            for (int i = 0; i < 4; i++) qa[i] = *(float4*)&Qs[(srow + i) * TLD + d];
#pragma unroll
            for (int j = 0; j < 4; j++) kb[j] = *(float4*)&Ks[(scol + j) * TLD + d];
#pragma unroll
            for (int i = 0; i < 4; i++)
#pragma unroll
                for (int j = 0; j < 4; j++) {
                    s[i][j] += qa[i].x * kb[j].x + qa[i].y * kb[j].y
                             + qa[i].z * kb[j].z + qa[i].w * kb[j].w;
                }
        }
#pragma unroll
        for (int i = 0; i < 4; i++)
#pragma unroll
            for (int j = 0; j < 4; j++)
                Ss[(srow + i) * TLD + scol + j] = s[i][j];
        __syncthreads();

        // Online softmax: row = tid/4, 4 threads per row (16 cols each)
        {
            const int row = tid >> 2;
            const int qq  = tid & 3;
            float* srcp = &Ss[row * TLD + qq * 16];
            float tm = -3.0e38f;
#pragma unroll
            for (int c = 0; c < 16; c++) tm = fmaxf(tm, srcp[c]);
            tm = fmaxf(tm, __shfl_xor_sync(0xffffffffu, tm, 1));
            tm = fmaxf(tm, __shfl_xor_sync(0xffffffffu, tm, 2));
            float mold = m_s[row];
            float mnew = fmaxf(mold, tm);
            float rs = 0.f;
#pragma unroll
            for (int c = 0; c < 16; c++) {
                float e = __expf(srcp[c] - mnew);
                srcp[c] = e;
                rs += e;
            }
            rs += __shfl_xor_sync(0xffffffffu, rs, 1);
            rs += __shfl_xor_sync(0xffffffffu, rs, 2);
            if (qq == 0) {
                float f = __expf(mold - mnew);
                m_s[row] = mnew;
                l_s[row] = l_s[row] * f + rs;
                f_s[row] = f;
            }
        }
        __syncthreads();

        // Rescale accumulators, then acc += P @ V
#pragma unroll
        for (int i = 0; i < 4; i++) {
            float f = f_s[srow + i];
#pragma unroll
            for (int j = 0; j < 4; j++) acc[i][j] *= f;
        }
        for (int k = 0; k < 64; k++) {
            float p[4], vv[4];
#pragma unroll
            for (int i = 0; i < 4; i++) p[i] = Ss[(srow + i) * TLD + k];
#pragma unroll
            for (int j = 0; j < 4; j++) vv[j] = Vs[k * TLD + scol + j];
#pragma unroll
            for (int i = 0; i < 4; i++)
#pragma unroll
                for (int j = 0; j < 4; j++) acc[i][j] += p[i] * vv[j];
        }
    }
    __syncthreads();

#pragma unroll
    for (int i = 0; i < 4; i++) {
        float inv = 1.0f / l_s[srow + i];
        int q = q0 + srow + i;
#pragma unroll
        for (int j = 0; j < 4; j++) {
            out[(size_t)(b * N_ + q) * D_ + h * DP_ + scol + j] = acc[i][j] * inv;
        }
    }
}

// ---------------------------------------------------------------------------
// Launch
// ---------------------------------------------------------------------------
extern "C" void kernel_launch(void* const* d_in, const int* in_sizes, int n_in,
                              void* d_out, int out_size)
{
    const float* x     = (const float*)d_in[0];
    const float* W_qkv = (const float*)d_in[1];
    const float* b_qkv = (const float*)d_in[2];
    const float* W_out = (const float*)d_in[3];
    const float* b_out = (const float*)d_in[4];
    float* out = (float*)d_out;

    float* qkv;  cudaGetSymbolAddress((void**)&qkv, g_qkv);
    float* attn; cudaGetSymbolAddress((void**)&attn, g_attn);

    // 1) QKV projection: [4096,1024] @ [1024,3072] + b
    {
        dim3 grid(EQ_ / BN, M_ROWS / BM);   // (24, 32)
        sgemm_bias_kernel<<<grid, 256>>>(x, W_qkv, b_qkv, qkv, M_ROWS, EQ_, D_);
    }

    // 2) Attention
    {
        const int smem = (4 * 64 * TLD + 3 * 64) * (int)sizeof(float);  // 70400 B
        cudaFuncSetAttribute(attn_kernel, cudaFuncAttributeMaxDynamicSharedMemorySize, smem);
        dim3 grid(N_ / 64, H_, B_);         // (32, 16, 2)
        attn_kernel<<<grid, 256, smem>>>(qkv, attn);
    }

    // 3) Output projection: [4096,1024] @ [1024,1024] + b
    {
        dim3 grid(D_ / BN, M_ROWS / BM);    // (8, 32)
        sgemm_bias_kernel<<<grid, 256>>>(attn, W_out, b_out, out, M_ROWS, D_, D_);
    }
}